// round 17
// baseline (speedup 1.0000x reference)
#include <cuda_runtime.h>
#include <cuda_bf16.h>
#include <cstdint>

// ContrastiveLoss B=8192 D=128 T=0.1, classes c=2*tt+tp in {0..3}
// Round 17: R16 + (1) col-flush via direct atomicAdd after shfl (removes the
// red-scratch smem stage and one barrier per tile), (2) scatter fused into
// prep (ballot ranks re-derived per block; removes a launch + newpos array).

#define B_SZ 8192
#define RSB  272u
#define ATILE 17408u              // 64 rows * 272
#define OFF_B   34816u            // + buf*34816 ; hi +0, lo +17408
#define OFF_CLS 104448u           // + buf*64
#define SMEM_BYTES (104448 + 128 + 1024)
#define NCTA 296

// ---------------------------------------------------------------- globals
__device__ __align__(256) __nv_bfloat16 g_hi[B_SZ * 128];
__device__ __align__(256) __nv_bfloat16 g_lo[B_SZ * 128];
__device__ int           g_cls_orig[B_SZ];
__device__ int           g_cls[B_SZ];
__device__ __align__(256) unsigned char g_clsb[B_SZ];
__device__ int           g_blkcnt[32][4];
__device__ int           g_cnt4[4];
__device__ int           g_joblist[8448];    // (mode<<16)|(x<<8)|d, grouped by x
__device__ int           g_njobs;
__device__ float         g_Ep[B_SZ];
__device__ float         g_En[B_SZ];
__device__ float         g_Ls[B_SZ];
__device__ float         g_rowval[B_SZ];
__device__ int           g_ticket;

// ---------------------------------------------------------------- helpers
__device__ __forceinline__ uint32_t smem_u32(const void* p) {
    uint32_t a;
    asm("{ .reg .u64 t; cvta.to.shared.u64 t, %1; cvt.u32.u64 %0, t; }" : "=r"(a) : "l"(p));
    return a;
}
__device__ __forceinline__ void cp16(uint32_t dst, const void* src) {
    asm volatile("cp.async.cg.shared.global [%0], [%1], 16;" :: "r"(dst), "l"(src) : "memory");
}
__device__ __forceinline__ void cp_commit() {
    asm volatile("cp.async.commit_group;" ::: "memory");
}
__device__ __forceinline__ void cp_wait0() {
    asm volatile("cp.async.wait_group 0;" ::: "memory");
}
__device__ __forceinline__ void cp_wait1() {
    asm volatile("cp.async.wait_group 1;" ::: "memory");
}
__device__ __forceinline__ void ldsm4(uint32_t* r, uint32_t addr) {
    asm volatile("ldmatrix.sync.aligned.m8n8.x4.shared.b16 {%0,%1,%2,%3}, [%4];"
                 : "=r"(r[0]), "=r"(r[1]), "=r"(r[2]), "=r"(r[3]) : "r"(addr));
}
__device__ __forceinline__ void mma_bf16(float* c, const uint32_t* a, uint32_t b0, uint32_t b1) {
    asm volatile(
        "mma.sync.aligned.m16n8k16.row.col.f32.bf16.bf16.f32 "
        "{%0,%1,%2,%3}, {%4,%5,%6,%7}, {%8,%9}, {%0,%1,%2,%3};"
        : "+f"(c[0]), "+f"(c[1]), "+f"(c[2]), "+f"(c[3])
        : "r"(a[0]), "r"(a[1]), "r"(a[2]), "r"(a[3]), "r"(b0), "r"(b1));
}
__device__ __forceinline__ float ex2f(float v) {
    float e;
    asm("ex2.approx.ftz.f32 %0, %1;" : "=f"(e) : "f"(v));
    return e;
}

__device__ __forceinline__ void load_tile64(uint32_t sdst_h, int rowbase, int tid) {
#pragma unroll
    for (int i = 0; i < 4; ++i) {
        int idx = tid + i * 256;
        int r = idx >> 4, c = idx & 15;
        uint32_t dst = sdst_h + (uint32_t)r * RSB + (uint32_t)c * 16u;
        cp16(dst, g_hi + (size_t)(rowbase + r) * 128 + c * 8);
        cp16(dst + ATILE, g_lo + (size_t)(rowbase + r) * 128 + c * 8);
    }
}

// ---------------------------------------------------------------- cls + counts + zero (+detect)
__global__ void cls_zero_kernel(const void* __restrict__ data_ix,
                                const void* __restrict__ tt,
                                const void* __restrict__ tp) {
    int b = blockIdx.x, tid = threadIdx.x;
    if (b < 32) {
        __shared__ int hc[4];
        __shared__ int bad;
        if (tid < 4) hc[tid] = 0;
        if (tid == 0) bad = 0;
        __syncthreads();
        {
            long long v = ((const long long*)data_ix)[(b & 15) * 256 + tid];
            if (v < 0 || v >= 100000) atomicOr(&bad, 1);
        }
        __syncthreads();
        const bool is64 = (bad == 0);
        int i = b * 256 + tid;
        int t, p;
        if (is64) {
            long long ix = ((const long long*)data_ix)[i];
            t = (int)((const long long*)tt)[ix];
            p = (int)((const long long*)tp)[ix];
        } else {
            int ix = ((const int*)data_ix)[i];
            t = ((const int*)tt)[ix];
            p = ((const int*)tp)[ix];
        }
        int c = t * 2 + p;
        g_cls_orig[i] = c;
        atomicAdd(&hc[c], 1);
        __syncthreads();
        if (tid < 4) g_blkcnt[b][tid] = hc[tid];
    } else if (b < 64) {
        int i = (b - 32) * 256 + tid;
        g_Ep[i] = 0.f; g_En[i] = 0.f; g_Ls[i] = 0.f;
        if (b == 32 && tid == 0) g_ticket = 0;
    }
}

// ---------------------------------------------------------------- sort + prep (fused)
// 32 CTAs x 256 thr. Each block: inlined scan of g_blkcnt -> ballot ranks for
// its 256 rows -> write sorted cls; then each warp normalizes/splits its 32
// rows (warp-wide) directly into the sorted g_hi/g_lo positions.
__global__ void sortprep_kernel(const float* __restrict__ F) {
    __shared__ int blkoff[32][4];
    __shared__ int wcnt[8][4];
    __shared__ int wbase[8][4];
    __shared__ int npos[256];
    int b = blockIdx.x, tid = threadIdx.x, lane = tid & 31, w = tid >> 5;

    if (tid < 128) {                       // inlined scan (redundant per block)
        int w2 = tid >> 5;
        int v = g_blkcnt[lane][w2];
        int own = v;
#pragma unroll
        for (int o = 1; o < 32; o <<= 1) {
            int u = __shfl_up_sync(0xffffffffu, v, o);
            if (lane >= o) v += u;
        }
        int total = __shfl_sync(0xffffffffu, v, 31);
        wcnt[0][w2] = total;
        __syncthreads();
        int base = 0;
        for (int c = 0; c < 4; ++c) base += (c < w2) ? wcnt[0][c] : 0;
        blkoff[lane][w2] = base + (v - own);
        if (lane == 0 && b == 0) g_cnt4[w2] = total;
    } else {
        __syncthreads();
    }
    __syncthreads();

    int i = b * 256 + tid;
    int c = g_cls_orig[i];
    unsigned b0 = __ballot_sync(0xffffffffu, c == 0);
    unsigned b1 = __ballot_sync(0xffffffffu, c == 1);
    unsigned b2 = __ballot_sync(0xffffffffu, c == 2);
    unsigned b3 = __ballot_sync(0xffffffffu, c == 3);
    unsigned mb = (c == 0) ? b0 : (c == 1) ? b1 : (c == 2) ? b2 : b3;
    int lanerank = __popc(mb & ((1u << lane) - 1u));
    if (lane == 0) {
        wcnt[w][0] = __popc(b0); wcnt[w][1] = __popc(b1);
        wcnt[w][2] = __popc(b2); wcnt[w][3] = __popc(b3);
    }
    __syncthreads();
    if (tid < 32) {
        int cc = tid >> 3, ww = tid & 7;
        int s = 0;
        for (int u = 0; u < ww; ++u) s += wcnt[u][cc];
        wbase[ww][cc] = s;
    }
    __syncthreads();
    int np = blkoff[b][c] + wbase[w][c] + lanerank;
    npos[tid] = np;
    g_cls[np] = c;
    g_clsb[np] = (unsigned char)c;
    __syncthreads();

    // normalize + split: each warp handles 32 consecutive rows of this block
    for (int r = 0; r < 32; ++r) {
        int row_i = b * 256 + w * 32 + r;
        int rnp = npos[w * 32 + r];
        const float* row = F + (size_t)row_i * 128;
        float v0 = row[lane], v1 = row[lane + 32], v2 = row[lane + 64], v3 = row[lane + 96];
        float ss = v0 * v0 + v1 * v1 + v2 * v2 + v3 * v3;
#pragma unroll
        for (int o = 16; o; o >>= 1) ss += __shfl_xor_sync(0xffffffffu, ss, o);
        float scale = sqrtf(14.4269504088896f) / sqrtf(ss);
        float g[4] = {v0 * scale, v1 * scale, v2 * scale, v3 * scale};
#pragma unroll
        for (int qq = 0; qq < 4; ++qq) {
            __nv_bfloat16 h = __float2bfloat16(g[qq]);
            __nv_bfloat16 lo = __float2bfloat16(g[qq] - __bfloat162float(h));
            g_hi[(size_t)rnp * 128 + lane + qq * 32] = h;
            g_lo[(size_t)rnp * 128 + lane + qq * 32] = lo;
        }
    }
}

// ---------------------------------------------------------------- job list (1 block, 128 thr)
__global__ void joblist_kernel() {
    __shared__ int woff[4];
    __shared__ unsigned char bc[128];
    int x = threadIdx.x;
    int lane = x & 31, w = x >> 5;
    {
        int c0 = g_cls[x * 64], c1 = g_cls[x * 64 + 63];
        bc[x] = (c0 == c1) ? (unsigned char)c0 : (unsigned char)255;
    }
    __syncthreads();
    int bcx = bc[x];
    int n = 0;
#pragma unroll 1
    for (int d = 0; d <= 64; ++d) {
        if (d == 64 && x >= 64) break;
        int tj = (x + d) & 127;
        int bcj = bc[tj];
        int xr = bcx ^ bcj;
        bool skip = (bcx < 4 && bcj < 4) && (xr != 1) && (xr != 2);
        if (!skip) ++n;
    }
    int v = n;
#pragma unroll
    for (int o = 1; o < 32; o <<= 1) {
        int u = __shfl_up_sync(0xffffffffu, v, o);
        if (lane >= o) v += u;
    }
    if (lane == 31) woff[w] = v;
    int ex = v - n;
    __syncthreads();
    if (x == 0) {
        int run = 0;
        for (int u = 0; u < 4; ++u) { int tmp = woff[u]; woff[u] = run; run += tmp; }
        g_njobs = run;
    }
    __syncthreads();
    int pos = woff[w] + ex;
#pragma unroll 1
    for (int d = 0; d <= 64; ++d) {
        if (d == 64 && x >= 64) break;
        int tj = (x + d) & 127;
        int bcj = bc[tj];
        int xr = bcx ^ bcj;
        bool pure = (bcx < 4 && bcj < 4);
        bool skip = pure && (xr != 1) && (xr != 2);
        if (!skip) {
            int mode = pure ? ((xr == 1) ? 1 : 2) : 0;
            g_joblist[pos++] = (mode << 16) | (x << 8) | d;
        }
    }
}

// ---------------------------------------------------------------- main kernel
__global__ void __launch_bounds__(256, 2) main_kernel() {
    extern __shared__ char smraw[];
    char* smp = (char*)(((uintptr_t)smraw + 1023) & ~(uintptr_t)1023);
    const uint32_t sb = smem_u32(smp);

    const int tid = threadIdx.x;
    const int l = tid & 31, wid = tid >> 5;
    const int warp_m = wid >> 2, warp_n = wid & 3;
    const int cta = blockIdx.x;

    const int M = g_njobs;
    const int jstart = (int)(((long long)cta * M) / NCTA);
    const int jend   = (int)(((long long)(cta + 1) * M) / NCTA);

    const uint32_t laneA = (uint32_t)((warp_m * 32 + (l & 15)) * (int)RSB + ((l >> 4) * 16));
    const uint32_t pAh = sb + laneA;
    const uint32_t pAl = sb + ATILE + laneA;
    const uint32_t laneB = (uint32_t)((warp_n * 16 + (l & 15)) * (int)RSB + ((l >> 4) * 16));

    float epos[4] = {0.f, 0.f, 0.f, 0.f};
    float eneg[4] = {0.f, 0.f, 0.f, 0.f};
    float lsum[4] = {0.f, 0.f, 0.f, 0.f};
    int pc[4], ncl[4];
    int curx = -1, buf = 0;

    auto flush_rows = [&](int fx) {
#pragma unroll
        for (int ri = 0; ri < 4; ++ri) {
            epos[ri] += __shfl_xor_sync(0xffffffffu, epos[ri], 1);
            epos[ri] += __shfl_xor_sync(0xffffffffu, epos[ri], 2);
            eneg[ri] += __shfl_xor_sync(0xffffffffu, eneg[ri], 1);
            eneg[ri] += __shfl_xor_sync(0xffffffffu, eneg[ri], 2);
            lsum[ri] += __shfl_xor_sync(0xffffffffu, lsum[ri], 1);
            lsum[ri] += __shfl_xor_sync(0xffffffffu, lsum[ri], 2);
        }
        if ((l & 3) == 0) {
#pragma unroll
            for (int ri = 0; ri < 4; ++ri) {
                int row = warp_m * 32 + (ri >> 1) * 16 + (ri & 1) * 8 + (l >> 2);
                int gi = fx * 64 + row;
                atomicAdd(&g_Ep[gi], epos[ri]);
                atomicAdd(&g_En[gi], eneg[ri]);
                atomicAdd(&g_Ls[gi], lsum[ri]);
            }
        }
#pragma unroll
        for (int ri = 0; ri < 4; ++ri) { epos[ri] = 0.f; eneg[ri] = 0.f; lsum[ri] = 0.f; }
    };

    for (int j = jstart; j < jend; ++j) {
        const int job = g_joblist[j];
        const int x = (job >> 8) & 255, d = job & 255, mode = job >> 16;
        const int tj = (x + d) & 127;

        if (x != curx) {
            if (curx >= 0) flush_rows(curx);
            load_tile64(sb + 0u, x * 64, tid);
            load_tile64(sb + OFF_B, tj * 64, tid);
            if (tid < 4) cp16(sb + OFF_CLS + tid * 16u, g_clsb + tj * 64 + tid * 16);
            cp_commit();
            cp_wait0();
            __syncthreads();
            buf = 0;
            curx = x;
#pragma unroll
            for (int ri = 0; ri < 4; ++ri) {
                int row = warp_m * 32 + (ri >> 1) * 16 + (ri & 1) * 8 + (l >> 2);
                int cr = g_cls[x * 64 + row];
                pc[ri] = cr ^ 1;
                ncl[ri] = cr ^ 2;
            }
        }

        bool pf = false;
        if (j + 1 < jend) {
            int nj = g_joblist[j + 1];
            if (((nj >> 8) & 255) == x) {
                int ntj = (x + (nj & 255)) & 127;
                load_tile64(sb + OFF_B + (uint32_t)(buf ^ 1) * 34816u, ntj * 64, tid);
                if (tid < 4)
                    cp16(sb + OFF_CLS + (uint32_t)(buf ^ 1) * 64u + tid * 16u,
                         g_clsb + ntj * 64 + tid * 16);
                cp_commit();
                cp_wait1();
                pf = true;
            }
        }
        if (!pf) cp_wait0();
        __syncthreads();

        // ---------------- MMA: 64x64 tile, K=128, 3 splits
        const uint32_t pBh = sb + OFF_B + (uint32_t)buf * 34816u + laneB;
        const uint32_t pBl = pBh + ATILE;

        float acc[2][2][4];
#pragma unroll
        for (int mf = 0; mf < 2; ++mf)
#pragma unroll
            for (int nf = 0; nf < 2; ++nf)
#pragma unroll
                for (int c4 = 0; c4 < 4; ++c4) acc[mf][nf][c4] = 0.f;

#pragma unroll 1
        for (int ks = 0; ks < 8; ++ks) {
            const uint32_t ko = (uint32_t)ks * 32u;
            uint32_t aH[2][4], aL[2][4], bh[4], bl[4];
            ldsm4(aH[0], pAh + ko);
            ldsm4(aH[1], pAh + 16u * RSB + ko);
            ldsm4(aL[0], pAl + ko);
            ldsm4(aL[1], pAl + 16u * RSB + ko);
            ldsm4(bh, pBh + ko);
            ldsm4(bl, pBl + ko);
#pragma unroll
            for (int nf = 0; nf < 2; ++nf)
#pragma unroll
                for (int mf = 0; mf < 2; ++mf)
                    mma_bf16(acc[mf][nf], aH[mf], bh[nf], bh[nf + 2]);
#pragma unroll
            for (int nf = 0; nf < 2; ++nf)
#pragma unroll
                for (int mf = 0; mf < 2; ++mf)
                    mma_bf16(acc[mf][nf], aH[mf], bl[nf], bl[nf + 2]);
#pragma unroll
            for (int nf = 0; nf < 2; ++nf)
#pragma unroll
                for (int mf = 0; mf < 2; ++mf)
                    mma_bf16(acc[mf][nf], aL[mf], bh[nf], bh[nf + 2]);
        }

        // ---------------- epilogue (col-flush via direct atomics, no smem stage)
        const bool doCol = (d != 0);
        if (mode == 0) {
            const uint32_t clsb_s = sb + OFF_CLS + (uint32_t)buf * 64u +
                                    (uint32_t)(warp_n * 16 + 2 * (l & 3));
#pragma unroll
            for (int nf = 0; nf < 2; ++nf) {
                unsigned short cw;
                asm volatile("ld.shared.u16 %0, [%1];" : "=h"(cw) : "r"(clsb_s + (uint32_t)nf * 8u));
                const int cj0 = cw & 0xff, cj1 = cw >> 8;
                float cE0 = 0.f, cE1 = 0.f, cN0 = 0.f, cN1 = 0.f, cL0 = 0.f, cL1 = 0.f;
#pragma unroll
                for (int ri = 0; ri < 4; ++ri) {
                    float v0 = acc[ri >> 1][nf][(ri & 1) * 2 + 0];
                    float v1 = acc[ri >> 1][nf][(ri & 1) * 2 + 1];
                    float e0 = ex2f(v0), e1 = ex2f(v1);
                    if (cj0 == pc[ri]) { epos[ri] += e0; lsum[ri] += v0; cE0 += e0; cL0 += v0; }
                    else if (cj0 == ncl[ri]) { eneg[ri] += e0; cN0 += e0; }
                    if (cj1 == pc[ri]) { epos[ri] += e1; lsum[ri] += v1; cE1 += e1; cL1 += v1; }
                    else if (cj1 == ncl[ri]) { eneg[ri] += e1; cN1 += e1; }
                }
                if (doCol) {
#pragma unroll
                    for (int s = 4; s <= 16; s <<= 1) {
                        cE0 += __shfl_xor_sync(0xffffffffu, cE0, s);
                        cE1 += __shfl_xor_sync(0xffffffffu, cE1, s);
                        cN0 += __shfl_xor_sync(0xffffffffu, cN0, s);
                        cN1 += __shfl_xor_sync(0xffffffffu, cN1, s);
                        cL0 += __shfl_xor_sync(0xffffffffu, cL0, s);
                        cL1 += __shfl_xor_sync(0xffffffffu, cL1, s);
                    }
                    if ((l >> 2) == 0) {
                        int gi = tj * 64 + warp_n * 16 + nf * 8 + 2 * l;
                        atomicAdd(&g_Ep[gi], cE0);     atomicAdd(&g_Ep[gi + 1], cE1);
                        atomicAdd(&g_En[gi], cN0);     atomicAdd(&g_En[gi + 1], cN1);
                        atomicAdd(&g_Ls[gi], cL0);     atomicAdd(&g_Ls[gi + 1], cL1);
                    }
                }
            }
        } else if (mode == 1) {
#pragma unroll
            for (int nf = 0; nf < 2; ++nf) {
                float cE0 = 0.f, cE1 = 0.f, cL0 = 0.f, cL1 = 0.f;
#pragma unroll
                for (int ri = 0; ri < 4; ++ri) {
                    float v0 = acc[ri >> 1][nf][(ri & 1) * 2 + 0];
                    float v1 = acc[ri >> 1][nf][(ri & 1) * 2 + 1];
                    float e0 = ex2f(v0), e1 = ex2f(v1);
                    epos[ri] += e0 + e1;
                    lsum[ri] += v0 + v1;
                    cE0 += e0; cE1 += e1; cL0 += v0; cL1 += v1;
                }
                if (doCol) {
#pragma unroll
                    for (int s = 4; s <= 16; s <<= 1) {
                        cE0 += __shfl_xor_sync(0xffffffffu, cE0, s);
                        cE1 += __shfl_xor_sync(0xffffffffu, cE1, s);
                        cL0 += __shfl_xor_sync(0xffffffffu, cL0, s);
                        cL1 += __shfl_xor_sync(0xffffffffu, cL1, s);
                    }
                    if ((l >> 2) == 0) {
                        int gi = tj * 64 + warp_n * 16 + nf * 8 + 2 * l;
                        atomicAdd(&g_Ep[gi], cE0);     atomicAdd(&g_Ep[gi + 1], cE1);
                        atomicAdd(&g_Ls[gi], cL0);     atomicAdd(&g_Ls[gi + 1], cL1);
                    }
                }
            }
        } else {
#pragma unroll
            for (int nf = 0; nf < 2; ++nf) {
                float cN0 = 0.f, cN1 = 0.f;
#pragma unroll
                for (int ri = 0; ri < 4; ++ri) {
                    float v0 = acc[ri >> 1][nf][(ri & 1) * 2 + 0];
                    float v1 = acc[ri >> 1][nf][(ri & 1) * 2 + 1];
                    float e0 = ex2f(v0), e1 = ex2f(v1);
                    eneg[ri] += e0 + e1;
                    cN0 += e0; cN1 += e1;
                }
                if (doCol) {
#pragma unroll
                    for (int s = 4; s <= 16; s <<= 1) {
                        cN0 += __shfl_xor_sync(0xffffffffu, cN0, s);
                        cN1 += __shfl_xor_sync(0xffffffffu, cN1, s);
                    }
                    if ((l >> 2) == 0) {
                        int gi = tj * 64 + warp_n * 16 + nf * 8 + 2 * l;
                        atomicAdd(&g_En[gi], cN0);     atomicAdd(&g_En[gi + 1], cN1);
                    }
                }
            }
        }
        // end-of-tile barrier: protects B[buf] overwrite by next iteration's
        // prefetch and A region on x-change. (red-scratch barrier removed.)
        __syncthreads();
        if (pf) buf ^= 1;
    }

    if (curx >= 0) flush_rows(curx);
}

// ---------------------------------------------------------------- rowval + ticketed sum
__global__ void rowval_sum_kernel(float* __restrict__ out) {
    __shared__ bool is_last;
    __shared__ float s[256];
    int tid = threadIdx.x;
    int i = blockIdx.x * 256 + tid;
    {
        float Ep = g_Ep[i], En = g_En[i], Ls = g_Ls[i];
        int ci = g_cls[i];
        int pcnt = g_cnt4[ci ^ 1];
        int ncnt = g_cnt4[ci ^ 2];
        float val = 0.f;
        if (pcnt > 0 && ncnt > 0)
            val = (Ls * 0.6931471805599453f - (float)pcnt * logf(Ep + En)) / (float)pcnt;
        g_rowval[i] = val;
    }
    __threadfence();
    __syncthreads();
    if (tid == 0) is_last = (atomicAdd(&g_ticket, 1) == gridDim.x - 1);
    __syncthreads();
    if (is_last) {
        float acc = 0.f;
        for (int k = tid; k < B_SZ; k += 256) acc += g_rowval[k];
        s[tid] = acc;
        __syncthreads();
        for (int o = 128; o; o >>= 1) {
            if (tid < o) s[tid] += s[tid + o];
            __syncthreads();
        }
        if (tid == 0) out[0] = -s[0] / (float)B_SZ;
    }
}

// ---------------------------------------------------------------- launch
extern "C" void kernel_launch(void* const* d_in, const int* in_sizes, int n_in,
                              void* d_out, int out_size) {
    const float* F = (const float*)d_in[0];
    const void* dix = d_in[1];
    const void* tt  = d_in[2];
    const void* tp  = d_in[3];
    float* out = (float*)d_out;

    cls_zero_kernel<<<64, 256>>>(dix, tt, tp);
    sortprep_kernel<<<32, 256>>>(F);
    joblist_kernel<<<1, 128>>>();

    cudaFuncSetAttribute(main_kernel, cudaFuncAttributeMaxDynamicSharedMemorySize, SMEM_BYTES);
    main_kernel<<<NCTA, 256, SMEM_BYTES>>>();

    rowval_sum_kernel<<<32, 256>>>(out);
}